// round 1
// baseline (speedup 1.0000x reference)
#include <cuda_runtime.h>
#include <math.h>

// Problem constants
#define CB   4096     // batch B
#define CDIN 1024     // D_IN
#define CD   256      // D
#define CK   1024     // K clusters
#define CL   32768    // L queue_n rows
#define CKQ  4096     // K*Q_MULT queue_k rows
#define PSPLIT 8      // j-splits for LSE partials
#define INV_TEMP (1.0f/0.07f)

// ------------------------- scratch (__device__ globals; no runtime alloc) -------------------------
static __device__ float g_F1[CB*CD];
static __device__ float g_ctx1[CK*CD];
static __device__ float g_ctx2[CK*CD];
static __device__ float g_qn[CL*CD];
static __device__ float g_qk[CKQ*CD];
static __device__ float g_L[CB*CK];          // logits -> assign (in-place), reused per view
static __device__ float g_aggraw[CK*CD];
static __device__ float g_aggk1[CK*CD];
static __device__ float g_norm1[CK];
static __device__ float g_norm2[CK];
static __device__ float g_lposN[CB];
static __device__ float g_lposK[CK];
static __device__ float g_pmN[CB*PSPLIT];
static __device__ float g_psN[CB*PSPLIT];
static __device__ float g_pmK[CK*PSPLIT];
static __device__ float g_psK[CK*PSPLIT];

// ------------------------- helpers -------------------------
__device__ __forceinline__ float gumbelf(float u) {
    u = u * (1.0f - 2e-6f) + 1e-6f;
    return -logf(-logf(u));
}

// ------------------------- row l2norm (D=256), optional per-row divisor (+EPS) -------------------------
// block = 64 threads, one row per block; in-place safe (each thread touches only its own float4)
__global__ void k_l2norm(const float* __restrict__ in, float* __restrict__ out,
                         const float* __restrict__ divisor) {
    int r = blockIdx.x, t = threadIdx.x;
    __shared__ float sh[2];
    float4 v = reinterpret_cast<const float4*>(in)[r*64 + t];
    if (divisor) {
        float d = 1.0f / (divisor[r] + 1e-8f);
        v.x *= d; v.y *= d; v.z *= d; v.w *= d;
    }
    float ss = v.x*v.x + v.y*v.y + v.z*v.z + v.w*v.w;
    #pragma unroll
    for (int o = 16; o; o >>= 1) ss += __shfl_xor_sync(0xffffffffu, ss, o);
    if ((t & 31) == 0) sh[t >> 5] = ss;
    __syncthreads();
    float s = rsqrtf(fmaxf(sh[0] + sh[1], 1e-12f));
    v.x *= s; v.y *= s; v.z *= s; v.w *= s;
    reinterpret_cast<float4*>(out)[r*64 + t] = v;
}

// queue = l2norm(2*l2norm(queue_k) + qnoise), fused
__global__ void k_queue_combine(const float* __restrict__ qk, const float* __restrict__ noise,
                                float* __restrict__ out) {
    int r = blockIdx.x, t = threadIdx.x;  // 64 threads
    __shared__ float sh[2];
    float4 v = reinterpret_cast<const float4*>(qk)[r*64 + t];
    float ss = v.x*v.x + v.y*v.y + v.z*v.z + v.w*v.w;
    #pragma unroll
    for (int o = 16; o; o >>= 1) ss += __shfl_xor_sync(0xffffffffu, ss, o);
    if ((t & 31) == 0) sh[t >> 5] = ss;
    __syncthreads();
    float s1 = 2.0f * rsqrtf(fmaxf(sh[0] + sh[1], 1e-12f));
    float4 n = reinterpret_cast<const float4*>(noise)[r*64 + t];
    float4 w = make_float4(v.x*s1 + n.x, v.y*s1 + n.y, v.z*s1 + n.z, v.w*s1 + n.w);
    __syncthreads();
    float ss2 = w.x*w.x + w.y*w.y + w.z*w.z + w.w*w.w;
    #pragma unroll
    for (int o = 16; o; o >>= 1) ss2 += __shfl_xor_sync(0xffffffffu, ss2, o);
    if ((t & 31) == 0) sh[t >> 5] = ss2;
    __syncthreads();
    float s2 = rsqrtf(fmaxf(sh[0] + sh[1], 1e-12f));
    w.x *= s2; w.y *= s2; w.z *= s2; w.w *= s2;
    reinterpret_cast<float4*>(out)[r*64 + t] = w;
}

// ------------------------- GEMMs: 64x64 tile, TK=16, 256 threads, 4x4 per thread -------------------------
// NN: C[M,N] = A[M,Kd] @ B[Kd,N]
__global__ void k_gemm_nn(const float* __restrict__ A, const float* __restrict__ Bm,
                          float* __restrict__ C, int M, int N, int Kd) {
    __shared__ float As[16][68];
    __shared__ float Bs[16][64];
    int tid = threadIdx.x;
    int tx = tid & 15, ty = tid >> 4;
    int m0 = blockIdx.x * 64, n0 = blockIdx.y * 64;
    int ar = tid >> 2, ac = (tid & 3) << 2;
    int br = tid >> 4, bc = (tid & 15) << 2;
    float acc[4][4] = {};
    for (int k0 = 0; k0 < Kd; k0 += 16) {
        float4 av = *reinterpret_cast<const float4*>(&A[(m0 + ar)*Kd + k0 + ac]);
        float4 bv = *reinterpret_cast<const float4*>(&Bm[(k0 + br)*N + n0 + bc]);
        __syncthreads();
        As[ac+0][ar] = av.x; As[ac+1][ar] = av.y; As[ac+2][ar] = av.z; As[ac+3][ar] = av.w;
        *reinterpret_cast<float4*>(&Bs[br][bc]) = bv;
        __syncthreads();
        #pragma unroll
        for (int k = 0; k < 16; k++) {
            float4 a4 = *reinterpret_cast<const float4*>(&As[k][ty << 2]);
            float4 b4 = *reinterpret_cast<const float4*>(&Bs[k][tx << 2]);
            float aa[4] = {a4.x, a4.y, a4.z, a4.w};
            float bb[4] = {b4.x, b4.y, b4.z, b4.w};
            #pragma unroll
            for (int r = 0; r < 4; r++)
                #pragma unroll
                for (int c = 0; c < 4; c++) acc[r][c] = fmaf(aa[r], bb[c], acc[r][c]);
        }
    }
    #pragma unroll
    for (int r = 0; r < 4; r++) {
        float4 o = make_float4(acc[r][0], acc[r][1], acc[r][2], acc[r][3]);
        *reinterpret_cast<float4*>(&C[(m0 + (ty << 2) + r)*N + n0 + (tx << 2)]) = o;
    }
}

// NT: C[M,N] = A[M,Kd] @ B[N,Kd]^T
__global__ void k_gemm_nt(const float* __restrict__ A, const float* __restrict__ Bm,
                          float* __restrict__ C, int M, int N, int Kd) {
    __shared__ float As[16][68];
    __shared__ float Bs[16][68];
    int tid = threadIdx.x;
    int tx = tid & 15, ty = tid >> 4;
    int m0 = blockIdx.x * 64, n0 = blockIdx.y * 64;
    int ar = tid >> 2, ac = (tid & 3) << 2;
    float acc[4][4] = {};
    for (int k0 = 0; k0 < Kd; k0 += 16) {
        float4 av = *reinterpret_cast<const float4*>(&A[(m0 + ar)*Kd + k0 + ac]);
        float4 bv = *reinterpret_cast<const float4*>(&Bm[(n0 + ar)*Kd + k0 + ac]);
        __syncthreads();
        As[ac+0][ar] = av.x; As[ac+1][ar] = av.y; As[ac+2][ar] = av.z; As[ac+3][ar] = av.w;
        Bs[ac+0][ar] = bv.x; Bs[ac+1][ar] = bv.y; Bs[ac+2][ar] = bv.z; Bs[ac+3][ar] = bv.w;
        __syncthreads();
        #pragma unroll
        for (int k = 0; k < 16; k++) {
            float4 a4 = *reinterpret_cast<const float4*>(&As[k][ty << 2]);
            float4 b4 = *reinterpret_cast<const float4*>(&Bs[k][tx << 2]);
            float aa[4] = {a4.x, a4.y, a4.z, a4.w};
            float bb[4] = {b4.x, b4.y, b4.z, b4.w};
            #pragma unroll
            for (int r = 0; r < 4; r++)
                #pragma unroll
                for (int c = 0; c < 4; c++) acc[r][c] = fmaf(aa[r], bb[c], acc[r][c]);
        }
    }
    #pragma unroll
    for (int r = 0; r < 4; r++) {
        float4 o = make_float4(acc[r][0], acc[r][1], acc[r][2], acc[r][3]);
        *reinterpret_cast<float4*>(&C[(m0 + (ty << 2) + r)*N + n0 + (tx << 2)]) = o;
    }
}

// TN: C[M,N] = sum_b A[b,m]*B[b,n]   (A:[Kb,M], B:[Kb,N], both row-major)
__global__ void k_gemm_tn(const float* __restrict__ A, const float* __restrict__ Bm,
                          float* __restrict__ C, int M, int N, int Kb) {
    __shared__ float As[16][64];
    __shared__ float Bs[16][64];
    int tid = threadIdx.x;
    int tx = tid & 15, ty = tid >> 4;
    int m0 = blockIdx.x * 64, n0 = blockIdx.y * 64;
    int kr = tid >> 4, kc = (tid & 15) << 2;
    float acc[4][4] = {};
    for (int b0 = 0; b0 < Kb; b0 += 16) {
        float4 av = *reinterpret_cast<const float4*>(&A[(b0 + kr)*M + m0 + kc]);
        float4 bv = *reinterpret_cast<const float4*>(&Bm[(b0 + kr)*N + n0 + kc]);
        __syncthreads();
        *reinterpret_cast<float4*>(&As[kr][kc]) = av;
        *reinterpret_cast<float4*>(&Bs[kr][kc]) = bv;
        __syncthreads();
        #pragma unroll
        for (int k = 0; k < 16; k++) {
            float4 a4 = *reinterpret_cast<const float4*>(&As[k][ty << 2]);
            float4 b4 = *reinterpret_cast<const float4*>(&Bs[k][tx << 2]);
            float aa[4] = {a4.x, a4.y, a4.z, a4.w};
            float bb[4] = {b4.x, b4.y, b4.z, b4.w};
            #pragma unroll
            for (int r = 0; r < 4; r++)
                #pragma unroll
                for (int c = 0; c < 4; c++) acc[r][c] = fmaf(aa[r], bb[c], acc[r][c]);
        }
    }
    #pragma unroll
    for (int r = 0; r < 4; r++) {
        float4 o = make_float4(acc[r][0], acc[r][1], acc[r][2], acc[r][3]);
        *reinterpret_cast<float4*>(&C[(m0 + (ty << 2) + r)*N + n0 + (tx << 2)]) = o;
    }
}

// ------------------------- fused NT-GEMM + online logsumexp (the 68.7 GF hot path) -------------------------
// A:[Mq,256] (unit rows), Q:[Nq,256] (unit rows). CTA: 64 rows x jspan cols in 64-chunks.
// Writes per-row (m,s) partials at [row*PSPLIT + blockIdx.y].
__global__ void k_lse_nt(const float* __restrict__ A, const float* __restrict__ Q,
                         float* __restrict__ pm, float* __restrict__ ps,
                         int jspan, float scale) {
    __shared__ float As[16][68];
    __shared__ float Bs[16][68];
    int tid = threadIdx.x;
    int tx = tid & 15, ty = tid >> 4;
    int m0 = blockIdx.x * 64;
    int jbase = blockIdx.y * jspan;
    int ar = tid >> 2, ac = (tid & 3) << 2;
    float mrun[4], srun[4];
    #pragma unroll
    for (int r = 0; r < 4; r++) { mrun[r] = -INFINITY; srun[r] = 0.0f; }

    for (int jc = 0; jc < jspan; jc += 64) {
        int n0 = jbase + jc;
        float acc[4][4] = {};
        #pragma unroll 4
        for (int k0 = 0; k0 < CD; k0 += 16) {
            float4 av = *reinterpret_cast<const float4*>(&A[(m0 + ar)*CD + k0 + ac]);
            float4 bv = *reinterpret_cast<const float4*>(&Q[(n0 + ar)*CD + k0 + ac]);
            __syncthreads();
            As[ac+0][ar] = av.x; As[ac+1][ar] = av.y; As[ac+2][ar] = av.z; As[ac+3][ar] = av.w;
            Bs[ac+0][ar] = bv.x; Bs[ac+1][ar] = bv.y; Bs[ac+2][ar] = bv.z; Bs[ac+3][ar] = bv.w;
            __syncthreads();
            #pragma unroll
            for (int k = 0; k < 16; k++) {
                float4 a4 = *reinterpret_cast<const float4*>(&As[k][ty << 2]);
                float4 b4 = *reinterpret_cast<const float4*>(&Bs[k][tx << 2]);
                float aa[4] = {a4.x, a4.y, a4.z, a4.w};
                float bb[4] = {b4.x, b4.y, b4.z, b4.w};
                #pragma unroll
                for (int r = 0; r < 4; r++)
                    #pragma unroll
                    for (int c = 0; c < 4; c++) acc[r][c] = fmaf(aa[r], bb[c], acc[r][c]);
            }
        }
        // online logsumexp update across tx-group (16 lanes own one row-quad's 64 cols)
        #pragma unroll
        for (int r = 0; r < 4; r++) {
            float v0 = acc[r][0]*scale, v1 = acc[r][1]*scale, v2 = acc[r][2]*scale, v3 = acc[r][3]*scale;
            float vm = fmaxf(fmaxf(v0, v1), fmaxf(v2, v3));
            #pragma unroll
            for (int o = 8; o; o >>= 1) vm = fmaxf(vm, __shfl_xor_sync(0xffffffffu, vm, o));
            float mn = fmaxf(mrun[r], vm);
            float e = __expf(v0 - mn) + __expf(v1 - mn) + __expf(v2 - mn) + __expf(v3 - mn);
            #pragma unroll
            for (int o = 8; o; o >>= 1) e += __shfl_xor_sync(0xffffffffu, e, o);
            srun[r] = srun[r] * __expf(mrun[r] - mn) + e;
            mrun[r] = mn;
        }
    }
    if (tx == 0) {
        #pragma unroll
        for (int r = 0; r < 4; r++) {
            int row = m0 + (ty << 2) + r;
            pm[row*PSPLIT + blockIdx.y] = mrun[r];
            ps[row*PSPLIT + blockIdx.y] = srun[r];
        }
    }
}

// ------------------------- gumbel-softmax (soft, in-place) + hard argmax -------------------------
// one row (K=1024) per block of 256 threads, 4 contiguous elems/thread
__global__ void k_softmax_gumbel(float* __restrict__ Lm, const float* __restrict__ uS,
                                 const float* __restrict__ uH, float* __restrict__ assignOut) {
    int b = blockIdx.x, t = threadIdx.x;
    __shared__ float sh[8];
    __shared__ float shv[8];
    __shared__ int shi[8];
    float4* L4 = reinterpret_cast<float4*>(Lm) + b*(CK/4);
    float4 l = L4[t];
    float4 us = (reinterpret_cast<const float4*>(uS) + b*(CK/4))[t];
    float4 uh = (reinterpret_cast<const float4*>(uH) + b*(CK/4))[t];
    float zs[4] = { (l.x + gumbelf(us.x))*2.0f, (l.y + gumbelf(us.y))*2.0f,
                    (l.z + gumbelf(us.z))*2.0f, (l.w + gumbelf(us.w))*2.0f };
    float zh[4] = { l.x + gumbelf(uh.x), l.y + gumbelf(uh.y),
                    l.z + gumbelf(uh.z), l.w + gumbelf(uh.w) };
    // row max of zs
    float vm = fmaxf(fmaxf(zs[0], zs[1]), fmaxf(zs[2], zs[3]));
    #pragma unroll
    for (int o = 16; o; o >>= 1) vm = fmaxf(vm, __shfl_xor_sync(0xffffffffu, vm, o));
    if ((t & 31) == 0) sh[t >> 5] = vm;
    __syncthreads();
    float bm = sh[0];
    #pragma unroll
    for (int i = 1; i < 8; i++) bm = fmaxf(bm, sh[i]);
    float e[4];
    float es = 0.0f;
    #pragma unroll
    for (int j = 0; j < 4; j++) { e[j] = __expf(zs[j] - bm); es += e[j]; }
    #pragma unroll
    for (int o = 16; o; o >>= 1) es += __shfl_xor_sync(0xffffffffu, es, o);
    __syncthreads();
    if ((t & 31) == 0) sh[t >> 5] = es;
    __syncthreads();
    float S = 0.0f;
    #pragma unroll
    for (int i = 0; i < 8; i++) S += sh[i];
    float inv = 1.0f / S;
    L4[t] = make_float4(e[0]*inv, e[1]*inv, e[2]*inv, e[3]*inv);
    // argmax of zh (first occurrence on ties, like jnp.argmax)
    float bv = zh[0]; int bi = t*4;
    #pragma unroll
    for (int j = 1; j < 4; j++) if (zh[j] > bv) { bv = zh[j]; bi = t*4 + j; }
    #pragma unroll
    for (int o = 16; o; o >>= 1) {
        float ov = __shfl_xor_sync(0xffffffffu, bv, o);
        int   oi = __shfl_xor_sync(0xffffffffu, bi, o);
        if (ov > bv || (ov == bv && oi < bi)) { bv = ov; bi = oi; }
    }
    if ((t & 31) == 0) { shv[t >> 5] = bv; shi[t >> 5] = bi; }
    __syncthreads();
    if (t == 0 && assignOut) {
        float fbv = shv[0]; int fbi = shi[0];
        #pragma unroll
        for (int i = 1; i < 8; i++)
            if (shv[i] > fbv || (shv[i] == fbv && shi[i] < fbi)) { fbv = shv[i]; fbi = shi[i]; }
        assignOut[b] = (float)fbi;
    }
}

// column sums of assign [CB, CK] -> norm[CK]
__global__ void k_colsum(const float* __restrict__ A, float* __restrict__ norm) {
    int col = blockIdx.x * 256 + threadIdx.x;
    float s0 = 0, s1 = 0, s2 = 0, s3 = 0;
    for (int b = 0; b < CB; b += 4) {
        s0 += A[(b+0)*CK + col];
        s1 += A[(b+1)*CK + col];
        s2 += A[(b+2)*CK + col];
        s3 += A[(b+3)*CK + col];
    }
    norm[col] = (s0 + s1) + (s2 + s3);
}

// per-row dot of two [R,256] matrices (l_pos)
__global__ void k_rowdot(const float* __restrict__ A, const float* __restrict__ Bv,
                         float* __restrict__ out) {
    int r = blockIdx.x, t = threadIdx.x;  // 32 threads
    const float4* a4 = reinterpret_cast<const float4*>(A) + r*64;
    const float4* b4 = reinterpret_cast<const float4*>(Bv) + r*64;
    float4 a = a4[t], b = b4[t];
    float s = a.x*b.x + a.y*b.y + a.z*b.z + a.w*b.w;
    a = a4[t + 32]; b = b4[t + 32];
    s += a.x*b.x + a.y*b.y + a.z*b.z + a.w*b.w;
    #pragma unroll
    for (int o = 16; o; o >>= 1) s += __shfl_xor_sync(0xffffffffu, s, o);
    if (t == 0) out[r] = s;
}

__device__ __forceinline__ float blockReduceSum1024(float v, float* sh) {
    int t = threadIdx.x;
    #pragma unroll
    for (int o = 16; o; o >>= 1) v += __shfl_xor_sync(0xffffffffu, v, o);
    if ((t & 31) == 0) sh[t >> 5] = v;
    __syncthreads();
    float s = 0.0f;
    if (t < 32) {
        s = sh[t];
        #pragma unroll
        for (int o = 16; o; o >>= 1) s += __shfl_xor_sync(0xffffffffu, s, o);
    }
    return s;  // valid in warp 0
}

// combine partials + l_pos, produce final loss scalar
__global__ void k_final(const float* __restrict__ pmN, const float* __restrict__ psN,
                        const float* __restrict__ lposN,
                        const float* __restrict__ pmK, const float* __restrict__ psK,
                        const float* __restrict__ lposK,
                        float* __restrict__ outLoss) {
    int t = threadIdx.x;  // 1024 threads
    __shared__ float sh[32];
    float accN = 0.0f;
    for (int r = t; r < CB; r += 1024) {
        float lp = lposN[r] * INV_TEMP;
        float m = lp, s = 1.0f;
        #pragma unroll
        for (int p = 0; p < PSPLIT; p++) {
            float mp = pmN[r*PSPLIT + p], sp = psN[r*PSPLIT + p];
            float mn = fmaxf(m, mp);
            s = s * __expf(m - mn) + sp * __expf(mp - mn);
            m = mn;
        }
        accN += m + logf(s) - lp;
    }
    float sumN = blockReduceSum1024(accN, sh);
    __syncthreads();
    float accK = 0.0f;
    {
        int r = t;  // CK == 1024
        float lp = lposK[r] * INV_TEMP;
        float m = lp, s = 1.0f;
        #pragma unroll
        for (int p = 0; p < PSPLIT; p++) {
            float mp = pmK[r*PSPLIT + p], sp = psK[r*PSPLIT + p];
            float mn = fmaxf(m, mp);
            s = s * __expf(m - mn) + sp * __expf(mp - mn);
            m = mn;
        }
        accK = m + logf(s) - lp;
    }
    float sumK = blockReduceSum1024(accK, sh);
    if (t == 0) *outLoss = sumN / (float)CB + sumK / (float)CK;
}

// ------------------------- host launcher -------------------------
extern "C" void kernel_launch(void* const* d_in, const int* in_sizes, int n_in,
                              void* d_out, int out_size) {
    const float* x1       = (const float*)d_in[0];
    const float* x2       = (const float*)d_in[1];
    const float* W1       = (const float*)d_in[2];
    const float* W2       = (const float*)d_in[3];
    const float* context1 = (const float*)d_in[4];
    const float* context2 = (const float*)d_in[5];
    const float* queue_n  = (const float*)d_in[6];
    const float* queue_k  = (const float*)d_in[7];
    const float* u1a      = (const float*)d_in[8];
    const float* u1b      = (const float*)d_in[9];
    const float* u2a      = (const float*)d_in[10];
    const float* u2b      = (const float*)d_in[11];
    const float* qnoise   = (const float*)d_in[12];

    float* out       = (float*)d_out;
    float* outAssign = out;                        // [4096]
    float* outF2     = out + CB;                   // agg_n_2 = feat_2, [4096,256]
    float* outAggk2  = outF2 + (size_t)CB*CD;      // agg_k_2, [1024,256]
    float* outLoss   = outAggk2 + (size_t)CK*CD;   // scalar

    float *pF1, *pCtx1, *pCtx2, *pQn, *pQk, *pL, *pAggraw, *pAggk1,
          *pNorm1, *pNorm2, *pLposN, *pLposK, *pPmN, *pPsN, *pPmK, *pPsK;
    cudaGetSymbolAddress((void**)&pF1,     g_F1);
    cudaGetSymbolAddress((void**)&pCtx1,   g_ctx1);
    cudaGetSymbolAddress((void**)&pCtx2,   g_ctx2);
    cudaGetSymbolAddress((void**)&pQn,     g_qn);
    cudaGetSymbolAddress((void**)&pQk,     g_qk);
    cudaGetSymbolAddress((void**)&pL,      g_L);
    cudaGetSymbolAddress((void**)&pAggraw, g_aggraw);
    cudaGetSymbolAddress((void**)&pAggk1,  g_aggk1);
    cudaGetSymbolAddress((void**)&pNorm1,  g_norm1);
    cudaGetSymbolAddress((void**)&pNorm2,  g_norm2);
    cudaGetSymbolAddress((void**)&pLposN,  g_lposN);
    cudaGetSymbolAddress((void**)&pLposK,  g_lposK);
    cudaGetSymbolAddress((void**)&pPmN,    g_pmN);
    cudaGetSymbolAddress((void**)&pPsN,    g_psN);
    cudaGetSymbolAddress((void**)&pPmK,    g_pmK);
    cudaGetSymbolAddress((void**)&pPsK,    g_psK);

    // normalize contexts / queues
    k_l2norm<<<CK, 64>>>(context1, pCtx1, nullptr);
    k_l2norm<<<CK, 64>>>(context2, pCtx2, nullptr);
    k_l2norm<<<CL, 64>>>(queue_n, pQn, nullptr);
    k_queue_combine<<<CKQ, 64>>>(queue_k, qnoise, pQk);

    // features
    k_gemm_nn<<<dim3(CB/64, CD/64), 256>>>(x1, W1, pF1, CB, CD, CDIN);
    k_l2norm<<<CB, 64>>>(pF1, pF1, nullptr);
    k_gemm_nn<<<dim3(CB/64, CD/64), 256>>>(x2, W2, outF2, CB, CD, CDIN);
    k_l2norm<<<CB, 64>>>(outF2, outF2, nullptr);

    // view 1
    k_gemm_nt<<<dim3(CB/64, CK/64), 256>>>(pF1, pCtx1, pL, CB, CK, CD);
    k_softmax_gumbel<<<CB, 256>>>(pL, u1a, u1b, outAssign);
    k_colsum<<<CK/256, 256>>>(pL, pNorm1);
    k_gemm_tn<<<dim3(CK/64, CD/64), 256>>>(pL, pF1, pAggraw, CK, CD, CB);
    k_l2norm<<<CK, 64>>>(pAggraw, pAggk1, pNorm1);

    // view 2
    k_gemm_nt<<<dim3(CB/64, CK/64), 256>>>(outF2, pCtx2, pL, CB, CK, CD);
    k_softmax_gumbel<<<CB, 256>>>(pL, u2a, u2b, nullptr);
    k_colsum<<<CK/256, 256>>>(pL, pNorm2);
    k_gemm_tn<<<dim3(CK/64, CD/64), 256>>>(pL, outF2, pAggraw, CK, CD, CB);
    k_l2norm<<<CK, 64>>>(pAggraw, outAggk2, pNorm2);

    // positives
    k_rowdot<<<CB, 32>>>(pF1, outF2, pLposN);
    k_rowdot<<<CK, 32>>>(pAggk1, outAggk2, pLposK);

    // streamed GEMM + logsumexp over negatives
    k_lse_nt<<<dim3(CB/64, PSPLIT), 256>>>(pF1, pQn, pPmN, pPsN, CL/PSPLIT, INV_TEMP);
    k_lse_nt<<<dim3(CK/64, PSPLIT), 256>>>(pAggk1, pQk, pPmK, pPsK, CKQ/PSPLIT, INV_TEMP);

    // final scalar loss
    k_final<<<1, 1024>>>(pPmN, pPsN, pLposN, pPmK, pPsK, pLposK, outLoss);
}

// round 4
// speedup vs baseline: 2.6002x; 2.6002x over previous
#include <cuda_runtime.h>
#include <cuda_bf16.h>
#include <math.h>
#include <stdint.h>

// Problem constants
#define CB   4096     // batch B
#define CDIN 1024     // D_IN
#define CD   256      // D
#define CK   1024     // K clusters
#define CL   32768    // L queue_n rows
#define CKQ  4096     // K*Q_MULT queue_k rows
#define PSPLIT 8      // j-splits for LSE partials
#define PPART (PSPLIT*2)  // 2 warp-halves per j-split write separate partials
#define INV_TEMP (1.0f/0.07f)

// ------------------------- scratch (__device__ globals; no runtime alloc) -------------------------
static __device__ __align__(16) float g_F1[CB*CD];
static __device__ __align__(16) float g_ctx1[CK*CD];
static __device__ __align__(16) float g_ctx2[CK*CD];
static __device__ __align__(16) float g_L[CB*CK];
static __device__ __align__(16) float g_aggraw[CK*CD];
static __device__ __align__(16) float g_aggk1[CK*CD];
static __device__ float g_norm1[CK];
static __device__ float g_norm2[CK];
static __device__ float g_lposN[CB];
static __device__ float g_lposK[CK];
static __device__ float g_pmN[CB*PPART];
static __device__ float g_psN[CB*PPART];
static __device__ float g_pmK[CK*PPART];
static __device__ float g_psK[CK*PPART];
// bf16 copies for the tensor-core LSE path
static __device__ __align__(16) __nv_bfloat16 g_F1b[CB*CD];
static __device__ __align__(16) __nv_bfloat16 g_aggk1b[CK*CD];
static __device__ __align__(16) __nv_bfloat16 g_qnb[CL*CD];
static __device__ __align__(16) __nv_bfloat16 g_qkb[CKQ*CD];

// ------------------------- PTX helpers (sm_80-era only: compute_103 virtual arch!) -------------------------
__device__ __forceinline__ uint32_t smem_u32(const void* p) {
    uint32_t a;
    asm("{ .reg .u64 t; cvta.to.shared.u64 t, %1; cvt.u32.u64 %0, t; }" : "=r"(a) : "l"(p));
    return a;
}
__device__ __forceinline__ void cp16(uint32_t dst, const void* src) {
    asm volatile("cp.async.cg.shared.global [%0], [%1], 16;" :: "r"(dst), "l"(src));
}
#define CP_COMMIT() asm volatile("cp.async.commit_group;" ::: "memory")
#define CP_WAIT0()  asm volatile("cp.async.wait_group 0;" ::: "memory")

__device__ __forceinline__ void ldm_x4(uint32_t r[4], uint32_t addr) {
    asm volatile("ldmatrix.sync.aligned.m8n8.x4.shared.b16 {%0,%1,%2,%3}, [%4];"
                 : "=r"(r[0]), "=r"(r[1]), "=r"(r[2]), "=r"(r[3]) : "r"(addr));
}
__device__ __forceinline__ void mma_bf16(float c[4], const uint32_t a[4], uint32_t b0, uint32_t b1) {
    asm volatile("mma.sync.aligned.m16n8k16.row.col.f32.bf16.bf16.f32 "
                 "{%0,%1,%2,%3}, {%4,%5,%6,%7}, {%8,%9}, {%0,%1,%2,%3};"
                 : "+f"(c[0]), "+f"(c[1]), "+f"(c[2]), "+f"(c[3])
                 : "r"(a[0]), "r"(a[1]), "r"(a[2]), "r"(a[3]), "r"(b0), "r"(b1));
}

// ------------------------- helpers -------------------------
__device__ __forceinline__ float gumbelf(float u) {
    u = u * (1.0f - 2e-6f) + 1e-6f;
    return -logf(-logf(u));
}

// ------------------------- row l2norm (D=256) w/ optional divisor, fp32+bf16 outputs -------------------------
__global__ void k_l2norm(const float* __restrict__ in, float* __restrict__ outf,
                         __nv_bfloat16* __restrict__ outb, const float* __restrict__ divisor) {
    int r = blockIdx.x, t = threadIdx.x;  // 64 threads
    __shared__ float sh[2];
    float4 v = reinterpret_cast<const float4*>(in)[r*64 + t];
    if (divisor) {
        float d = 1.0f / (divisor[r] + 1e-8f);
        v.x *= d; v.y *= d; v.z *= d; v.w *= d;
    }
    float ss = v.x*v.x + v.y*v.y + v.z*v.z + v.w*v.w;
    #pragma unroll
    for (int o = 16; o; o >>= 1) ss += __shfl_xor_sync(0xffffffffu, ss, o);
    if ((t & 31) == 0) sh[t >> 5] = ss;
    __syncthreads();
    float s = rsqrtf(fmaxf(sh[0] + sh[1], 1e-12f));
    v.x *= s; v.y *= s; v.z *= s; v.w *= s;
    if (outf) reinterpret_cast<float4*>(outf)[r*64 + t] = v;
    if (outb) {
        __nv_bfloat162 lo = __floats2bfloat162_rn(v.x, v.y);
        __nv_bfloat162 hi = __floats2bfloat162_rn(v.z, v.w);
        uint2 u = make_uint2(*(uint32_t*)&lo, *(uint32_t*)&hi);
        reinterpret_cast<uint2*>(outb)[r*64 + t] = u;
    }
}

// queue = l2norm(2*l2norm(queue_k) + qnoise), fused; bf16 output
__global__ void k_queue_combine(const float* __restrict__ qk, const float* __restrict__ noise,
                                __nv_bfloat16* __restrict__ outb) {
    int r = blockIdx.x, t = threadIdx.x;  // 64 threads
    __shared__ float sh[2];
    float4 v = reinterpret_cast<const float4*>(qk)[r*64 + t];
    float ss = v.x*v.x + v.y*v.y + v.z*v.z + v.w*v.w;
    #pragma unroll
    for (int o = 16; o; o >>= 1) ss += __shfl_xor_sync(0xffffffffu, ss, o);
    if ((t & 31) == 0) sh[t >> 5] = ss;
    __syncthreads();
    float s1 = 2.0f * rsqrtf(fmaxf(sh[0] + sh[1], 1e-12f));
    float4 n = reinterpret_cast<const float4*>(noise)[r*64 + t];
    float4 w = make_float4(v.x*s1 + n.x, v.y*s1 + n.y, v.z*s1 + n.z, v.w*s1 + n.w);
    __syncthreads();
    float ss2 = w.x*w.x + w.y*w.y + w.z*w.z + w.w*w.w;
    #pragma unroll
    for (int o = 16; o; o >>= 1) ss2 += __shfl_xor_sync(0xffffffffu, ss2, o);
    if ((t & 31) == 0) sh[t >> 5] = ss2;
    __syncthreads();
    float s2 = rsqrtf(fmaxf(sh[0] + sh[1], 1e-12f));
    w.x *= s2; w.y *= s2; w.z *= s2; w.w *= s2;
    __nv_bfloat162 lo = __floats2bfloat162_rn(w.x, w.y);
    __nv_bfloat162 hi = __floats2bfloat162_rn(w.z, w.w);
    uint2 u = make_uint2(*(uint32_t*)&lo, *(uint32_t*)&hi);
    reinterpret_cast<uint2*>(outb)[r*64 + t] = u;
}

// ------------------------- fp32 SIMT GEMMs (64x64 tile, 4x4/thread) -------------------------
__global__ void k_gemm_nn(const float* __restrict__ A, const float* __restrict__ Bm,
                          float* __restrict__ C, int M, int N, int Kd) {
    __shared__ float As[16][68];
    __shared__ float Bs[16][64];
    int tid = threadIdx.x;
    int tx = tid & 15, ty = tid >> 4;
    int m0 = blockIdx.x * 64, n0 = blockIdx.y * 64;
    int ar = tid >> 2, ac = (tid & 3) << 2;
    int br = tid >> 4, bc = (tid & 15) << 2;
    float acc[4][4] = {};
    for (int k0 = 0; k0 < Kd; k0 += 16) {
        float4 av = *reinterpret_cast<const float4*>(&A[(m0 + ar)*Kd + k0 + ac]);
        float4 bv = *reinterpret_cast<const float4*>(&Bm[(k0 + br)*N + n0 + bc]);
        __syncthreads();
        As[ac+0][ar] = av.x; As[ac+1][ar] = av.y; As[ac+2][ar] = av.z; As[ac+3][ar] = av.w;
        *reinterpret_cast<float4*>(&Bs[br][bc]) = bv;
        __syncthreads();
        #pragma unroll
        for (int k = 0; k < 16; k++) {
            float4 a4 = *reinterpret_cast<const float4*>(&As[k][ty << 2]);
            float4 b4 = *reinterpret_cast<const float4*>(&Bs[k][tx << 2]);
            float aa[4] = {a4.x, a4.y, a4.z, a4.w};
            float bb[4] = {b4.x, b4.y, b4.z, b4.w};
            #pragma unroll
            for (int r = 0; r < 4; r++)
                #pragma unroll
                for (int c = 0; c < 4; c++) acc[r][c] = fmaf(aa[r], bb[c], acc[r][c]);
        }
    }
    #pragma unroll
    for (int r = 0; r < 4; r++) {
        float4 o = make_float4(acc[r][0], acc[r][1], acc[r][2], acc[r][3]);
        *reinterpret_cast<float4*>(&C[(m0 + (ty << 2) + r)*N + n0 + (tx << 2)]) = o;
    }
}

__global__ void k_gemm_nt(const float* __restrict__ A, const float* __restrict__ Bm,
                          float* __restrict__ C, int M, int N, int Kd) {
    __shared__ float As[16][68];
    __shared__ float Bs[16][68];
    int tid = threadIdx.x;
    int tx = tid & 15, ty = tid >> 4;
    int m0 = blockIdx.x * 64, n0 = blockIdx.y * 64;
    int ar = tid >> 2, ac = (tid & 3) << 2;
    float acc[4][4] = {};
    for (int k0 = 0; k0 < Kd; k0 += 16) {
        float4 av = *reinterpret_cast<const float4*>(&A[(m0 + ar)*Kd + k0 + ac]);
        float4 bv = *reinterpret_cast<const float4*>(&Bm[(n0 + ar)*Kd + k0 + ac]);
        __syncthreads();
        As[ac+0][ar] = av.x; As[ac+1][ar] = av.y; As[ac+2][ar] = av.z; As[ac+3][ar] = av.w;
        Bs[ac+0][ar] = bv.x; Bs[ac+1][ar] = bv.y; Bs[ac+2][ar] = bv.z; Bs[ac+3][ar] = bv.w;
        __syncthreads();
        #pragma unroll
        for (int k = 0; k < 16; k++) {
            float4 a4 = *reinterpret_cast<const float4*>(&As[k][ty << 2]);
            float4 b4 = *reinterpret_cast<const float4*>(&Bs[k][tx << 2]);
            float aa[4] = {a4.x, a4.y, a4.z, a4.w};
            float bb[4] = {b4.x, b4.y, b4.z, b4.w};
            #pragma unroll
            for (int r = 0; r < 4; r++)
                #pragma unroll
                for (int c = 0; c < 4; c++) acc[r][c] = fmaf(aa[r], bb[c], acc[r][c]);
        }
    }
    #pragma unroll
    for (int r = 0; r < 4; r++) {
        float4 o = make_float4(acc[r][0], acc[r][1], acc[r][2], acc[r][3]);
        *reinterpret_cast<float4*>(&C[(m0 + (ty << 2) + r)*N + n0 + (tx << 2)]) = o;
    }
}

__global__ void k_gemm_tn(const float* __restrict__ A, const float* __restrict__ Bm,
                          float* __restrict__ C, int M, int N, int Kb) {
    __shared__ float As[16][64];
    __shared__ float Bs[16][64];
    int tid = threadIdx.x;
    int tx = tid & 15, ty = tid >> 4;
    int m0 = blockIdx.x * 64, n0 = blockIdx.y * 64;
    int kr = tid >> 4, kc = (tid & 15) << 2;
    float acc[4][4] = {};
    for (int b0 = 0; b0 < Kb; b0 += 16) {
        float4 av = *reinterpret_cast<const float4*>(&A[(b0 + kr)*M + m0 + kc]);
        float4 bv = *reinterpret_cast<const float4*>(&Bm[(b0 + kr)*N + n0 + kc]);
        __syncthreads();
        *reinterpret_cast<float4*>(&As[kr][kc]) = av;
        *reinterpret_cast<float4*>(&Bs[kr][kc]) = bv;
        __syncthreads();
        #pragma unroll
        for (int k = 0; k < 16; k++) {
            float4 a4 = *reinterpret_cast<const float4*>(&As[k][ty << 2]);
            float4 b4 = *reinterpret_cast<const float4*>(&Bs[k][tx << 2]);
            float aa[4] = {a4.x, a4.y, a4.z, a4.w};
            float bb[4] = {b4.x, b4.y, b4.z, b4.w};
            #pragma unroll
            for (int r = 0; r < 4; r++)
                #pragma unroll
                for (int c = 0; c < 4; c++) acc[r][c] = fmaf(aa[r], bb[c], acc[r][c]);
        }
    }
    #pragma unroll
    for (int r = 0; r < 4; r++) {
        float4 o = make_float4(acc[r][0], acc[r][1], acc[r][2], acc[r][3]);
        *reinterpret_cast<float4*>(&C[(m0 + (ty << 2) + r)*N + n0 + (tx << 2)]) = o;
    }
}

// ------------------------- HMMA bf16 LSE (the 68.7 GF hot path) -------------------------
// D[128,128] = A_tile[128,256] @ Q_tile[128,256]^T via mma.sync m16n8k16 (bf16 in, fp32 acc),
// fused with per-row online logsumexp. A stationary; Q double-buffered via cp.async.
// Smem rows padded to 264 bf16 (528B): 528 % 128 == 16 -> ldmatrix tiles conflict-free.
// Warp grid 4(mg) x 2(ng): each D-row is split across the two ng warps, so each
// (j-split, ng) pair writes its OWN partial slot: index blockIdx.y*2 + ng.
#define RSB 528u                        // bytes per smem row
#define LSE_TILE_BYTES (128u*RSB)       // 67584
#define LSE_SMEM (3u*LSE_TILE_BYTES + 128u)

__device__ __forceinline__ void lse_load_tile(uint32_t dstbase, const __nv_bfloat16* src) {
    int tid = threadIdx.x;  // 256 threads; 128 rows x 32 chunks of 16B
    #pragma unroll
    for (int i = 0; i < 16; i++) {
        int idx = tid + (i << 8);
        int row = idx >> 5;
        int c = idx & 31;
        cp16(dstbase + (uint32_t)row*RSB + (uint32_t)c*16u, src + row*256 + c*8);
    }
}

__global__ void __launch_bounds__(256, 1) k_lse_mma(
    const __nv_bfloat16* __restrict__ A, const __nv_bfloat16* __restrict__ Q,
    float* __restrict__ pm, float* __restrict__ ps, int jspan, float scale)
{
    extern __shared__ char smem_raw[];
    uint32_t base = (smem_u32(smem_raw) + 127u) & ~127u;
    uint32_t aBase  = base;
    uint32_t qBase0 = base + LSE_TILE_BYTES;
    uint32_t qBase1 = base + 2u*LSE_TILE_BYTES;

    int tid = threadIdx.x;
    int lane = tid & 31, w = tid >> 5;
    int mg = w & 3;          // 4 m-groups of 32 rows
    int ng = w >> 2;         // 2 n-groups of 64 cols
    int m0 = blockIdx.x * 128;
    int jbase = blockIdx.y * jspan;
    int nj = jspan >> 7;

    // ldmatrix lane geometry: tile = lane>>3, r = lane&7
    int lt = lane >> 3, lr = lane & 7;
    uint32_t aAddr = aBase + (uint32_t)(mg*32 + (lt & 1)*8 + lr)*RSB + (uint32_t)((lt >> 1)*8)*2u;
    uint32_t qOff = (uint32_t)(ng*64 + (lt >> 1)*8 + lr)*RSB + (uint32_t)((lt & 1)*8)*2u;

    lse_load_tile(aBase, A + (size_t)m0*256);
    lse_load_tile(qBase0, Q + (size_t)jbase*256);
    CP_COMMIT();

    float mrun[4], srun[4];
    #pragma unroll
    for (int s = 0; s < 4; s++) { mrun[s] = -INFINITY; srun[s] = 0.0f; }

    for (int jt = 0; jt < nj; jt++) {
        CP_WAIT0();
        __syncthreads();
        if (jt + 1 < nj) {
            lse_load_tile((jt & 1) ? qBase0 : qBase1, Q + (size_t)(jbase + (jt+1)*128)*256);
            CP_COMMIT();
        }
        uint32_t qB = (jt & 1) ? qBase1 : qBase0;

        float acc[2][8][4];
        #pragma unroll
        for (int mt = 0; mt < 2; mt++)
            #pragma unroll
            for (int nt = 0; nt < 8; nt++)
                #pragma unroll
                for (int c = 0; c < 4; c++) acc[mt][nt][c] = 0.0f;

        #pragma unroll 4
        for (int k0 = 0; k0 < 256; k0 += 16) {
            uint32_t a0[4], a1[4];
            ldm_x4(a0, aAddr + (uint32_t)k0*2u);
            ldm_x4(a1, aAddr + 16u*RSB + (uint32_t)k0*2u);
            #pragma unroll
            for (int np = 0; np < 4; np++) {
                uint32_t b[4];
                ldm_x4(b, qB + qOff + (uint32_t)np*16u*RSB + (uint32_t)k0*2u);
                mma_bf16(acc[0][2*np+0], a0, b[0], b[1]);
                mma_bf16(acc[0][2*np+1], a0, b[2], b[3]);
                mma_bf16(acc[1][2*np+0], a1, b[0], b[1]);
                mma_bf16(acc[1][2*np+1], a1, b[2], b[3]);
            }
        }

        // online logsumexp epilogue (quad lanes share a row; this warp's 64-col half)
        #pragma unroll
        for (int mt = 0; mt < 2; mt++) {
            #pragma unroll
            for (int rh = 0; rh < 2; rh++) {
                int s = mt*2 + rh;
                float v[16];
                float vm = -INFINITY;
                #pragma unroll
                for (int nt = 0; nt < 8; nt++) {
                    v[2*nt+0] = acc[mt][nt][rh*2+0] * scale;
                    v[2*nt+1] = acc[mt][nt][rh*2+1] * scale;
                    vm = fmaxf(vm, fmaxf(v[2*nt], v[2*nt+1]));
                }
                vm = fmaxf(vm, __shfl_xor_sync(0xffffffffu, vm, 1));
                vm = fmaxf(vm, __shfl_xor_sync(0xffffffffu, vm, 2));
                float mn = fmaxf(mrun[s], vm);
                float es = 0.0f;
                #pragma unroll
                for (int i = 0; i < 16; i++) es += __expf(v[i] - mn);
                es += __shfl_xor_sync(0xffffffffu, es, 1);
                es += __shfl_xor_sync(0xffffffffu, es, 2);
                srun[s] = srun[s] * __expf(mrun[s] - mn) + es;
                mrun[s] = mn;
            }
        }
    }

    if ((lane & 3) == 0) {
        int gid = lane >> 2;
        int slot = blockIdx.y*2 + ng;     // distinct slot per (j-split, column-half)
        #pragma unroll
        for (int mt = 0; mt < 2; mt++) {
            #pragma unroll
            for (int rh = 0; rh < 2; rh++) {
                int s = mt*2 + rh;
                int row = m0 + mg*32 + mt*16 + rh*8 + gid;
                pm[row*PPART + slot] = mrun[s];
                ps[row*PPART + slot] = srun[s];
            }
        }
    }
}

// ------------------------- gumbel-softmax (soft, in-place) + hard argmax -------------------------
__global__ void k_softmax_gumbel(float* __restrict__ Lm, const float* __restrict__ uS,
                                 const float* __restrict__ uH, float* __restrict__ assignOut) {
    int b = blockIdx.x, t = threadIdx.x;
    __shared__ float sh[8];
    __shared__ float shv[8];
    __shared__ int shi[8];
    float4* L4 = reinterpret_cast<float4*>(Lm) + b*(CK/4);
    float4 l = L4[t];
    float4 us = (reinterpret_cast<const float4*>(uS) + b*(CK/4))[t];
    float4 uh = (reinterpret_cast<const float4*>(uH) + b*(CK/4))[t];
    float zs[4] = { (l.x + gumbelf(us.x))*2.0f, (l.y + gumbelf(us.y))*2.0f,
                    (l.z + gumbelf(us.z))*2.0f, (l.w + gumbelf(us.w))*2.0f };
    float zh[4] = { l.x + gumbelf(uh.x), l.y + gumbelf(uh.y),
                    l.z + gumbelf(uh.z), l.w + gumbelf(uh.w) };
    float vm = fmaxf(fmaxf(zs[0], zs[1]), fmaxf(zs[2], zs[3]));
    #pragma unroll
    for (int o = 16; o; o >>= 1) vm = fmaxf(vm, __shfl_xor_sync(0xffffffffu, vm, o));
    if ((t & 31) == 0) sh[t >> 5] = vm;
    __syncthreads();
    float bm = sh[0];
    #pragma unroll
    for (int i = 1; i < 8; i++) bm = fmaxf(bm, sh[i]);
    float e[4];
    float es = 0.0f;
    #pragma unroll
    for (int j = 0; j < 4; j++) { e[j] = __expf(zs[j] - bm); es += e[j]; }
    #pragma unroll
    for (int o = 16; o; o >>= 1) es += __shfl_xor_sync(0xffffffffu, es, o);
    __syncthreads();
    if ((t & 31) == 0) sh[t >> 5] = es;
    __syncthreads();
    float S = 0.0f;
    #pragma unroll
    for (int i = 0; i < 8; i++) S += sh[i];
    float inv = 1.0f / S;
    L4[t] = make_float4(e[0]*inv, e[1]*inv, e[2]*inv, e[3]*inv);
    float bv = zh[0]; int bi = t*4;
    #pragma unroll
    for (int j = 1; j < 4; j++) if (zh[j] > bv) { bv = zh[j]; bi = t*4 + j; }
    #pragma unroll
    for (int o = 16; o; o >>= 1) {
        float ov = __shfl_xor_sync(0xffffffffu, bv, o);
        int   oi = __shfl_xor_sync(0xffffffffu, bi, o);
        if (ov > bv || (ov == bv && oi < bi)) { bv = ov; bi = oi; }
    }
    if ((t & 31) == 0) { shv[t >> 5] = bv; shi[t >> 5] = bi; }
    __syncthreads();
    if (t == 0 && assignOut) {
        float fbv = shv[0]; int fbi = shi[0];
        #pragma unroll
        for (int i = 1; i < 8; i++)
            if (shv[i] > fbv || (shv[i] == fbv && shi[i] < fbi)) { fbv = shv[i]; fbi = shi[i]; }
        assignOut[b] = (float)fbi;
    }
}

// column sums of assign [CB, CK] -> norm[CK]
__global__ void k_colsum(const float* __restrict__ A, float* __restrict__ norm) {
    int col = blockIdx.x * 256 + threadIdx.x;
    float s0 = 0, s1 = 0, s2 = 0, s3 = 0;
    for (int b = 0; b < CB; b += 4) {
        s0 += A[(b+0)*CK + col];
        s1 += A[(b+1)*CK + col];
        s2 += A[(b+2)*CK + col];
        s3 += A[(b+3)*CK + col];
    }
    norm[col] = (s0 + s1) + (s2 + s3);
}

// per-row dot of two [R,256] matrices (l_pos)
__global__ void k_rowdot(const float* __restrict__ A, const float* __restrict__ Bv,
                         float* __restrict__ out) {
    int r = blockIdx.x, t = threadIdx.x;  // 32 threads
    const float4* a4 = reinterpret_cast<const float4*>(A) + r*64;
    const float4* b4 = reinterpret_cast<const float4*>(Bv) + r*64;
    float4 a = a4[t], b = b4[t];
    float s = a.x*b.x + a.y*b.y + a.z*b.z + a.w*b.w;
    a = a4[t + 32]; b = b4[t + 32];
    s += a.x*b.x + a.y*b.y + a.z*b.z + a.w*b.w;
    #pragma unroll
    for (int o = 16; o; o >>= 1) s += __shfl_xor_sync(0xffffffffu, s, o);
    if (t == 0) out[r] = s;
}

__device__ __forceinline__ float blockReduceSum1024(float v, float* sh) {
    int t = threadIdx.x;
    #pragma unroll
    for (int o = 16; o; o >>= 1) v += __shfl_xor_sync(0xffffffffu, v, o);
    if ((t & 31) == 0) sh[t >> 5] = v;
    __syncthreads();
    float s = 0.0f;
    if (t < 32) {
        s = sh[t];
        #pragma unroll
        for (int o = 16; o; o >>= 1) s += __shfl_xor_sync(0xffffffffu, s, o);
    }
    return s;
}

__global__ void k_final(const float* __restrict__ pmN, const float* __restrict__ psN,
                        const float* __restrict__ lposN,
                        const float* __restrict__ pmK, const float* __restrict__ psK,
                        const float* __restrict__ lposK,
                        float* __restrict__ outLoss) {
    int t = threadIdx.x;
    __shared__ float sh[32];
    float accN = 0.0f;
    for (int r = t; r < CB; r += 1024) {
        float lp = lposN[r] * INV_TEMP;
        float m = lp, s = 1.0f;
        #pragma unroll
        for (int p = 0; p < PPART; p++) {
            float mp = pmN[r*PPART + p], sp = psN[r*PPART + p];
            float mn = fmaxf(m, mp);
            s = s * __expf(m - mn) + sp * __expf(mp - mn);
            m = mn;
        }
        accN += m + logf(s) - lp;
    }
    float sumN = blockReduceSum1024(accN, sh);
    __syncthreads();
    float accK = 0.0f;
    {
        int r = t;
        float lp = lposK[r] * INV_TEMP;
        float m = lp, s = 1.0f;
        #pragma unroll
        for (int p = 0; p < PPART; p++) {
            float mp = pmK[r*PPART + p], sp = psK[r*PPART + p];
            float mn = fmaxf(m, mp);
            s = s * __expf(m - mn) + sp * __expf(mp - mn);
            m = mn;
        }
        accK = m + logf(s) - lp;
    }
    float sumK = blockReduceSum1024(accK, sh);
    if (t == 0) *outLoss = sumN / (float)CB + sumK / (float)CK;
}

// ------------------------- host launcher -------------------------
extern "C" void kernel_launch(void* const* d_in, const int* in_sizes, int n_in,
                              void* d_out, int out_size) {
    const float* x1       = (const float*)d_in[0];
    const float* x2       = (const float*)d_in[1];
    const float* W1       = (const float*)d_in[2];
    const float* W2       = (const float*)d_in[3];
    const float* context1 = (const float*)d_in[4];
    const float* context2 = (const float*)d_in[5];
    const float* queue_n  = (const float*)d_in[6];
    const float* queue_k  = (const float*)d_in[7];
    const float* u1a      = (const float*)d_in[8];
    const float* u1b      = (const float*)d_in[9];
    const float* u2a      = (const float*)d_in[10];
    const float* u2b      = (const float*)d_in[11];
    const float* qnoise   = (const float*)d_in[12];

    float* out       = (float*)d_out;
    float* outAssign = out;
    float* outF2     = out + CB;
    float* outAggk2  = outF2 + (size_t)CB*CD;
    float* outLoss   = outAggk2 + (size_t)CK*CD;

    float *pF1, *pCtx1, *pCtx2, *pL, *pAggraw, *pAggk1,
          *pNorm1, *pNorm2, *pLposN, *pLposK, *pPmN, *pPsN, *pPmK, *pPsK;
    __nv_bfloat16 *pF1b, *pAggk1b, *pQnb, *pQkb;
    cudaGetSymbolAddress((void**)&pF1,     g_F1);
    cudaGetSymbolAddress((void**)&pCtx1,   g_ctx1);
    cudaGetSymbolAddress((void**)&pCtx2,   g_ctx2);
    cudaGetSymbolAddress((void**)&pL,      g_L);
    cudaGetSymbolAddress((void**)&pAggraw, g_aggraw);
    cudaGetSymbolAddress((void**)&pAggk1,  g_aggk1);
    cudaGetSymbolAddress((void**)&pNorm1,  g_norm1);
    cudaGetSymbolAddress((void**)&pNorm2,  g_norm2);
    cudaGetSymbolAddress((void**)&pLposN,  g_lposN);
    cudaGetSymbolAddress((void**)&pLposK,  g_lposK);
    cudaGetSymbolAddress((void**)&pPmN,    g_pmN);
    cudaGetSymbolAddress((void**)&pPsN,    g_psN);
    cudaGetSymbolAddress((void**)&pPmK,    g_pmK);
    cudaGetSymbolAddress((void**)&pPsK,    g_psK);
    cudaGetSymbolAddress((void**)&pF1b,    g_F1b);
    cudaGetSymbolAddress((void**)&pAggk1b, g_aggk1b);
    cudaGetSymbolAddress((void**)&pQnb,    g_qnb);
    cudaGetSymbolAddress((void**)&pQkb,    g_qkb);

    cudaFuncSetAttribute(k_lse_mma, cudaFuncAttributeMaxDynamicSharedMemorySize, LSE_SMEM);

    // normalize contexts / queues (queues -> bf16 for tensor path)
    k_l2norm<<<CK, 64>>>(context1, pCtx1, nullptr, nullptr);
    k_l2norm<<<CK, 64>>>(context2, pCtx2, nullptr, nullptr);
    k_l2norm<<<CL, 64>>>(queue_n, nullptr, pQnb, nullptr);
    k_queue_combine<<<CKQ, 64>>>(queue_k, qnoise, pQkb);

    // features
    k_gemm_nn<<<dim3(CB/64, CD/64), 256>>>(x1, W1, pF1, CB, CD, CDIN);
    k_l2norm<<<CB, 64>>>(pF1, pF1, pF1b, nullptr);
    k_gemm_nn<<<dim3(CB/64, CD/64), 256>>>(x2, W2, outF2, CB, CD, CDIN);
    k_l2norm<<<CB, 64>>>(outF2, outF2, nullptr, nullptr);

    // view 1
    k_gemm_nt<<<dim3(CB/64, CK/64), 256>>>(pF1, pCtx1, pL, CB, CK, CD);
    k_softmax_gumbel<<<CB, 256>>>(pL, u1a, u1b, outAssign);
    k_colsum<<<CK/256, 256>>>(pL, pNorm1);
    k_gemm_tn<<<dim3(CK/64, CD/64), 256>>>(pL, pF1, pAggraw, CK, CD, CB);
    k_l2norm<<<CK, 64>>>(pAggraw, pAggk1, pAggk1b, pNorm1);

    // view 2
    k_gemm_nt<<<dim3(CB/64, CK/64), 256>>>(outF2, pCtx2, pL, CB, CK, CD);
    k_softmax_gumbel<<<CB, 256>>>(pL, u2a, u2b, nullptr);
    k_colsum<<<CK/256, 256>>>(pL, pNorm2);
    k_gemm_tn<<<dim3(CK/64, CD/64), 256>>>(pL, outF2, pAggraw, CK, CD, CB);
    k_l2norm<<<CK, 64>>>(pAggraw, outAggk2, nullptr, pNorm2);

    // positives (fp32)
    k_rowdot<<<CB, 32>>>(pF1, outF2, pLposN);
    k_rowdot<<<CK, 32>>>(pAggk1, outAggk2, pLposK);

    // HMMA streamed GEMM + logsumexp over negatives
    k_lse_mma<<<dim3(CB/128, PSPLIT), 256, LSE_SMEM>>>(pF1b, pQnb, pPmN, pPsN, CL/PSPLIT, INV_TEMP);
    k_lse_mma<<<dim3(CK/128, PSPLIT), 256, LSE_SMEM>>>(pAggk1b, pQkb, pPmK, pPsK, CKQ/PSPLIT, INV_TEMP);

    // final scalar loss
    k_final<<<1, 1024>>>(pPmN, pPsN, pLposN, pPmK, pPsK, pLposK, outLoss);
}

// round 5
// speedup vs baseline: 4.3341x; 1.6668x over previous
#include <cuda_runtime.h>
#include <cuda_bf16.h>
#include <math.h>
#include <stdint.h>

// Problem constants
#define CB   4096     // batch B
#define CDIN 1024     // D_IN
#define CD   256      // D
#define CK   1024     // K clusters
#define CL   32768    // L queue_n rows
#define CKQ  4096     // K*Q_MULT queue_k rows
#define PSPLIT 8      // j-splits for LSE partials
#define PPART (PSPLIT*2)
#define INV_TEMP (1.0f/0.07f)

// ------------------------- scratch (__device__ globals; no runtime alloc) -------------------------
static __device__ __align__(16) float g_F1[CB*CD];
static __device__ __align__(16) float g_rawF[CB*CD];
static __device__ __align__(16) float g_L[CB*CK];
static __device__ __align__(16) float g_aggraw[CK*CD];
static __device__ __align__(16) float g_aggk1[CK*CD];
static __device__ __align__(16) float g_Cpart[8*CB*CD];   // split-K partials (max 8 x 1M)
static __device__ float g_norm1[CK];
static __device__ float g_norm2[CK];
static __device__ float g_lposN[CB];
static __device__ float g_lposK[CK];
static __device__ float g_pmN[CB*PPART];
static __device__ float g_psN[CB*PPART];
static __device__ float g_pmK[CK*PPART];
static __device__ float g_psK[CK*PPART];
// split-bf16 operand buffers (hi/lo pairs)
static __device__ __align__(16) __nv_bfloat16 g_xh[CB*CDIN];
static __device__ __align__(16) __nv_bfloat16 g_xl[CB*CDIN];
static __device__ __align__(16) __nv_bfloat16 g_wth[CD*CDIN];
static __device__ __align__(16) __nv_bfloat16 g_wtl[CD*CDIN];
static __device__ __align__(16) __nv_bfloat16 g_F1h[CB*CD];
static __device__ __align__(16) __nv_bfloat16 g_F1l[CB*CD];
static __device__ __align__(16) __nv_bfloat16 g_F2h[CB*CD];
static __device__ __align__(16) __nv_bfloat16 g_F2l[CB*CD];
static __device__ __align__(16) __nv_bfloat16 g_ctxh[CK*CD];
static __device__ __align__(16) __nv_bfloat16 g_ctxl[CK*CD];
static __device__ __align__(16) __nv_bfloat16 g_LTh[CK*CB];
static __device__ __align__(16) __nv_bfloat16 g_LTl[CK*CB];
static __device__ __align__(16) __nv_bfloat16 g_FTh[CD*CB];
static __device__ __align__(16) __nv_bfloat16 g_FTl[CD*CB];
static __device__ __align__(16) __nv_bfloat16 g_aggk1b[CK*CD];
static __device__ __align__(16) __nv_bfloat16 g_qnb[CL*CD];
static __device__ __align__(16) __nv_bfloat16 g_qkb[CKQ*CD];

// ------------------------- PTX helpers (sm_80-era only: compute_103 virtual arch!) -------------------------
__device__ __forceinline__ uint32_t smem_u32(const void* p) {
    uint32_t a;
    asm("{ .reg .u64 t; cvta.to.shared.u64 t, %1; cvt.u32.u64 %0, t; }" : "=r"(a) : "l"(p));
    return a;
}
__device__ __forceinline__ void cp16(uint32_t dst, const void* src) {
    asm volatile("cp.async.cg.shared.global [%0], [%1], 16;" :: "r"(dst), "l"(src));
}
#define CP_COMMIT() asm volatile("cp.async.commit_group;" ::: "memory")
#define CP_WAIT0()  asm volatile("cp.async.wait_group 0;" ::: "memory")

__device__ __forceinline__ void ldm_x4(uint32_t r[4], uint32_t addr) {
    asm volatile("ldmatrix.sync.aligned.m8n8.x4.shared.b16 {%0,%1,%2,%3}, [%4];"
                 : "=r"(r[0]), "=r"(r[1]), "=r"(r[2]), "=r"(r[3]) : "r"(addr));
}
__device__ __forceinline__ void mma_bf16(float c[4], const uint32_t a[4], uint32_t b0, uint32_t b1) {
    asm volatile("mma.sync.aligned.m16n8k16.row.col.f32.bf16.bf16.f32 "
                 "{%0,%1,%2,%3}, {%4,%5,%6,%7}, {%8,%9}, {%0,%1,%2,%3};"
                 : "+f"(c[0]), "+f"(c[1]), "+f"(c[2]), "+f"(c[3])
                 : "r"(a[0]), "r"(a[1]), "r"(a[2]), "r"(a[3]), "r"(b0), "r"(b1));
}

__device__ __forceinline__ float gumbelf(float u) {
    u = u * (1.0f - 2e-6f) + 1e-6f;
    return -logf(-logf(u));
}
__device__ __forceinline__ void split2(float v, __nv_bfloat16& h, __nv_bfloat16& l) {
    h = __float2bfloat16_rn(v);
    l = __float2bfloat16_rn(v - __bfloat162float(h));
}

// ------------------------- elementwise split / transpose-split -------------------------
// fp32 [n*4] -> hi/lo bf16
__global__ void k_split(const float* __restrict__ in, __nv_bfloat16* __restrict__ hi,
                        __nv_bfloat16* __restrict__ lo) {
    int i = blockIdx.x*256 + threadIdx.x;
    float4 v = reinterpret_cast<const float4*>(in)[i];
    __nv_bfloat16 h[4], l[4];
    split2(v.x, h[0], l[0]); split2(v.y, h[1], l[1]);
    split2(v.z, h[2], l[2]); split2(v.w, h[3], l[3]);
    reinterpret_cast<uint2*>(hi)[i] = *reinterpret_cast<uint2*>(h);
    reinterpret_cast<uint2*>(lo)[i] = *reinterpret_cast<uint2*>(l);
}

// in [R,C] fp32 -> out hi/lo bf16 [C,R]
__global__ void k_tsplit(const float* __restrict__ in, __nv_bfloat16* __restrict__ hiT,
                         __nv_bfloat16* __restrict__ loT, int R, int C) {
    __shared__ float t[32][33];
    int c0 = blockIdx.x*32, r0 = blockIdx.y*32;
    int tx = threadIdx.x, ty = threadIdx.y;  // 32 x 8
    #pragma unroll
    for (int i = 0; i < 4; i++)
        t[ty + i*8][tx] = in[(size_t)(r0 + ty + i*8)*C + c0 + tx];
    __syncthreads();
    #pragma unroll
    for (int i = 0; i < 4; i++) {
        float v = t[tx][ty + i*8];
        __nv_bfloat16 h, l;
        split2(v, h, l);
        size_t o = (size_t)(c0 + ty + i*8)*R + r0 + tx;
        hiT[o] = h; loT[o] = l;
    }
}

// sum split-K partials
__global__ void k_reduce(const float* __restrict__ part, float* __restrict__ outp,
                         int MN, int ks) {
    int i = blockIdx.x*256 + threadIdx.x;
    float s = 0.0f;
    for (int z = 0; z < ks; z++) s += part[(size_t)z*MN + i];
    outp[i] = s;
}

// ------------------------- row l2norm (D=256): fp32 + hi/lo bf16 outputs, optional divisor -------------------------
__global__ void k_l2norm(const float* __restrict__ in, float* __restrict__ outf,
                         __nv_bfloat16* __restrict__ outhi, __nv_bfloat16* __restrict__ outlo,
                         const float* __restrict__ divisor) {
    int r = blockIdx.x, t = threadIdx.x;  // 64 threads
    __shared__ float sh[2];
    float4 v = reinterpret_cast<const float4*>(in)[r*64 + t];
    if (divisor) {
        float d = 1.0f / (divisor[r] + 1e-8f);
        v.x *= d; v.y *= d; v.z *= d; v.w *= d;
    }
    float ss = v.x*v.x + v.y*v.y + v.z*v.z + v.w*v.w;
    #pragma unroll
    for (int o = 16; o; o >>= 1) ss += __shfl_xor_sync(0xffffffffu, ss, o);
    if ((t & 31) == 0) sh[t >> 5] = ss;
    __syncthreads();
    float s = rsqrtf(fmaxf(sh[0] + sh[1], 1e-12f));
    v.x *= s; v.y *= s; v.z *= s; v.w *= s;
    if (outf) reinterpret_cast<float4*>(outf)[r*64 + t] = v;
    if (outhi) {
        __nv_bfloat16 h[4], l[4];
        split2(v.x, h[0], l[0]); split2(v.y, h[1], l[1]);
        split2(v.z, h[2], l[2]); split2(v.w, h[3], l[3]);
        reinterpret_cast<uint2*>(outhi)[r*64 + t] = *reinterpret_cast<uint2*>(h);
        if (outlo) reinterpret_cast<uint2*>(outlo)[r*64 + t] = *reinterpret_cast<uint2*>(l);
    }
}

// queue = l2norm(2*l2norm(queue_k) + qnoise), fused; plain bf16 output
__global__ void k_queue_combine(const float* __restrict__ qk, const float* __restrict__ noise,
                                __nv_bfloat16* __restrict__ outb) {
    int r = blockIdx.x, t = threadIdx.x;  // 64 threads
    __shared__ float sh[2];
    float4 v = reinterpret_cast<const float4*>(qk)[r*64 + t];
    float ss = v.x*v.x + v.y*v.y + v.z*v.z + v.w*v.w;
    #pragma unroll
    for (int o = 16; o; o >>= 1) ss += __shfl_xor_sync(0xffffffffu, ss, o);
    if ((t & 31) == 0) sh[t >> 5] = ss;
    __syncthreads();
    float s1 = 2.0f * rsqrtf(fmaxf(sh[0] + sh[1], 1e-12f));
    float4 n = reinterpret_cast<const float4*>(noise)[r*64 + t];
    float4 w = make_float4(v.x*s1 + n.x, v.y*s1 + n.y, v.z*s1 + n.z, v.w*s1 + n.w);
    __syncthreads();
    float ss2 = w.x*w.x + w.y*w.y + w.z*w.z + w.w*w.w;
    #pragma unroll
    for (int o = 16; o; o >>= 1) ss2 += __shfl_xor_sync(0xffffffffu, ss2, o);
    if ((t & 31) == 0) sh[t >> 5] = ss2;
    __syncthreads();
    float s2 = rsqrtf(fmaxf(sh[0] + sh[1], 1e-12f));
    w.x *= s2; w.y *= s2; w.z *= s2; w.w *= s2;
    __nv_bfloat162 lo2 = __floats2bfloat162_rn(w.x, w.y);
    __nv_bfloat162 hi2 = __floats2bfloat162_rn(w.z, w.w);
    uint2 u = make_uint2(*(uint32_t*)&lo2, *(uint32_t*)&hi2);
    reinterpret_cast<uint2*>(outb)[r*64 + t] = u;
}

// ------------------------- split-bf16 NT GEMM: C[M,N] = A[M,K] @ B[N,K]^T -------------------------
// A,B given as hi/lo bf16 pairs (3-MMA emulation: hh + hl + lh), fp32 accumulate.
// 128x128 C tile, BK=64 chunks double-buffered via cp.async. Warp grid 4(m) x 2(n).
// Smem row stride 144B (64 bf16 + 8 pad): 144 % 128 == 16 -> ldmatrix conflict-free.
// Split-K via blockIdx.z writing disjoint partial buffers (deterministic).
#define GT_RS    144u
#define GT_TILE  (128u*GT_RS)     // 18432
#define GT_STAGE (4u*GT_TILE)     // 73728
#define GT_SMEM  (2u*GT_STAGE)    // 147456

__device__ __forceinline__ void gt_load(uint32_t dst, const __nv_bfloat16* src,
                                        int row0, int K, int kc) {
    int tid = threadIdx.x;  // 256 threads; 1024 chunks of 16B
    #pragma unroll
    for (int i = 0; i < 4; i++) {
        int idx = tid + (i << 8);
        int row = idx >> 3;
        int cc = (idx & 7) << 3;
        cp16(dst + (uint32_t)row*GT_RS + (uint32_t)cc*2u,
             src + (size_t)(row0 + row)*K + kc + cc);
    }
}

__global__ void __launch_bounds__(256, 1) k_mma3(
    const __nv_bfloat16* __restrict__ Ah, const __nv_bfloat16* __restrict__ Al,
    const __nv_bfloat16* __restrict__ Bh, const __nv_bfloat16* __restrict__ Bl,
    float* __restrict__ C, int M, int N, int K, int ksplit)
{
    extern __shared__ char sm[];
    uint32_t base = (smem_u32(sm) + 127u) & ~127u;
    int tid = threadIdx.x, lane = tid & 31, w = tid >> 5;
    int mg = w & 3, ng = w >> 2;
    int m0 = blockIdx.x * 128, n0 = blockIdx.y * 128;
    int Klocal = K / ksplit, kbase = blockIdx.z * Klocal;
    float* out = C + (size_t)blockIdx.z * M * N;
    int lt = lane >> 3, lr = lane & 7;
    uint32_t aOff = (uint32_t)(mg*32 + (lt & 1)*8 + lr)*GT_RS + (uint32_t)((lt >> 1)*8)*2u;
    uint32_t bOff = (uint32_t)(ng*64 + (lt >> 1)*8 + lr)*GT_RS + (uint32_t)((lt & 1)*8)*2u;

    {   // prologue: stage 0
        uint32_t s0 = base;
        gt_load(s0 + 0u*GT_TILE, Ah, m0, K, kbase);
        gt_load(s0 + 1u*GT_TILE, Al, m0, K, kbase);
        gt_load(s0 + 2u*GT_TILE, Bh, n0, K, kbase);
        gt_load(s0 + 3u*GT_TILE, Bl, n0, K, kbase);
        CP_COMMIT();
    }

    float acc[2][8][4];
    #pragma unroll
    for (int mt = 0; mt < 2; mt++)
        #pragma unroll
        for (int nt = 0; nt < 8; nt++)
            #pragma unroll
            for (int c = 0; c < 4; c++) acc[mt][nt][c] = 0.0f;

    int nk = Klocal >> 6;
    for (int kc = 0; kc < nk; kc++) {
        CP_WAIT0();
        __syncthreads();
        if (kc + 1 < nk) {
            uint32_t sn = base + (uint32_t)((kc + 1) & 1)*GT_STAGE;
            int kn = kbase + (kc + 1)*64;
            gt_load(sn + 0u*GT_TILE, Ah, m0, K, kn);
            gt_load(sn + 1u*GT_TILE, Al, m0, K, kn);
            gt_load(sn + 2u*GT_TILE, Bh, n0, K, kn);
            gt_load(sn + 3u*GT_TILE, Bl, n0, K, kn);
            CP_COMMIT();
        }
        uint32_t st = base + (uint32_t)(kc & 1)*GT_STAGE;
        #pragma unroll
        for (int k0 = 0; k0 < 64; k0 += 16) {
            uint32_t a0h[4], a1h[4], a0l[4], a1l[4];
            ldm_x4(a0h, st + 0u*GT_TILE + aOff + (uint32_t)k0*2u);
            ldm_x4(a1h, st + 0u*GT_TILE + aOff + 16u*GT_RS + (uint32_t)k0*2u);
            ldm_x4(a0l, st + 1u*GT_TILE + aOff + (uint32_t)k0*2u);
            ldm_x4(a1l, st + 1u*GT_TILE + aOff + 16u*GT_RS + (uint32_t)k0*2u);
            #pragma unroll
            for (int np = 0; np < 4; np++) {
                uint32_t bh[4], bl[4];
                ldm_x4(bh, st + 2u*GT_TILE + bOff + (uint32_t)np*16u*GT_RS + (uint32_t)k0*2u);
                ldm_x4(bl, st + 3u*GT_TILE + bOff + (uint32_t)np*16u*GT_RS + (uint32_t)k0*2u);
                // hi * hi
                mma_bf16(acc[0][2*np+0], a0h, bh[0], bh[1]);
                mma_bf16(acc[0][2*np+1], a0h, bh[2], bh[3]);
                mma_bf16(acc[1][2*np+0], a1h, bh[0], bh[1]);
                mma_bf16(acc[1][2*np+1], a1h, bh[2], bh[3]);
                // hi * lo
                mma_bf16(acc[0][2*np+0], a0h, bl[0], bl[1]);
                mma_bf16(acc[0][2*np+1], a0h, bl[2], bl[3]);
                mma_bf16(acc[1][2*np+0], a1h, bl[0], bl[1]);
                mma_bf16(acc[1][2*np+1], a1h, bl[2], bl[3]);
                // lo * hi
                mma_bf16(acc[0][2*np+0], a0l, bh[0], bh[1]);
                mma_bf16(acc[0][2*np+1], a0l, bh[2], bh[3]);
                mma_bf16(acc[1][2*np+0], a1l, bh[0], bh[1]);
                mma_bf16(acc[1][2*np+1], a1l, bh[2], bh[3]);
            }
        }
    }

    // store C (m16n8 fragment layout: c0,c1 row g; c2,c3 row g+8; cols 2q,2q+1)
    int gid = lane >> 2, qc = (lane & 3) << 1;
    #pragma unroll
    for (int mt = 0; mt < 2; mt++) {
        #pragma unroll
        for (int nt = 0; nt < 8; nt++) {
            int r0 = m0 + mg*32 + mt*16 + gid;
            int c0 = n0 + ng*64 + nt*8 + qc;
            float2 v0 = make_float2(acc[mt][nt][0], acc[mt][nt][1]);
            float2 v1 = make_float2(acc[mt][nt][2], acc[mt][nt][3]);
            *reinterpret_cast<float2*>(&out[(size_t)r0*N + c0]) = v0;
            *reinterpret_cast<float2*>(&out[(size_t)(r0 + 8)*N + c0]) = v1;
        }
    }
}

// ------------------------- HMMA bf16 LSE (validated in R4) -------------------------
#define RSB 528u
#define LSE_TILE_BYTES (128u*RSB)
#define LSE_SMEM (3u*LSE_TILE_BYTES + 128u)

__device__ __forceinline__ void lse_load_tile(uint32_t dstbase, const __nv_bfloat16* src) {
    int tid = threadIdx.x;
    #pragma unroll
    for (int i = 0; i < 16; i++) {
        int idx = tid + (i << 8);
        int row = idx >> 5;
        int c = idx & 31;
        cp16(dstbase + (uint32_t)row*RSB + (uint32_t)c*16u, src + row*256 + c*8);
    }
}

__global__ void __launch_bounds__(256, 1) k_lse_mma(
    const __nv_bfloat16* __restrict__ A, const __nv_bfloat16* __restrict__ Q,
    float* __restrict__ pm, float* __restrict__ ps, int jspan, float scale)
{
    extern __shared__ char smem_raw[];
    uint32_t base = (smem_u32(smem_raw) + 127u) & ~127u;
    uint32_t aBase  = base;
    uint32_t qBase0 = base + LSE_TILE_BYTES;
    uint32_t qBase1 = base + 2u*LSE_TILE_BYTES;

    int tid = threadIdx.x;
    int lane = tid & 31, w = tid >> 5;
    int mg = w & 3;
    int ng = w >> 2;
    int m0 = blockIdx.x * 128;
    int jbase = blockIdx.y * jspan;
    int nj = jspan >> 7;

    int lt = lane >> 3, lr = lane & 7;
    uint32_t aAddr = aBase + (uint32_t)(mg*32 + (lt & 1)*8 + lr)*RSB + (uint32_t)((lt >> 1)*8)*2u;
    uint32_t qOff = (uint32_t)(ng*64 + (lt >> 1)*8 + lr)*RSB + (uint32_t)((lt & 1)*8)*2u;

    lse_load_tile(aBase, A + (size_t)m0*256);
    lse_load_tile(qBase0, Q + (size_t)jbase*256);
    CP_COMMIT();

    float mrun[4], srun[4];
    #pragma unroll
    for (int s = 0; s < 4; s++) { mrun[s] = -INFINITY; srun[s] = 0.0f; }

    for (int jt = 0; jt < nj; jt++) {
        CP_WAIT0();
        __syncthreads();
        if (jt + 1 < nj) {
            lse_load_tile((jt & 1) ? qBase0 : qBase1, Q + (size_t)(jbase + (jt+1)*128)*256);
            CP_COMMIT();
        }
        uint32_t qB = (jt & 1) ? qBase1 : qBase0;

        float acc[2][8][4];
        #pragma unroll
        for (int mt = 0; mt < 2; mt++)
            #pragma unroll
            for (int nt = 0; nt < 8; nt++)
                #pragma unroll
                for (int c = 0; c < 4; c++) acc[mt][nt][c] = 0.0f;

        #pragma unroll 4
        for (int k0 = 0; k0 < 256; k0 += 16) {
            uint32_t a0[4], a1[4];
            ldm_x4(a0, aAddr + (uint32_t)k0*2u);
            ldm_x4(a1, aAddr + 16u*RSB + (uint32_t)k0*2u);
            #pragma unroll
            for (int np = 0; np < 4; np++) {
                uint32_t b[4];
                ldm_x4(b, qB + qOff + (uint32_t)np*16u*RSB + (uint32_t)k0*2u);
                mma_bf16(acc[0][2*np+0], a0, b[0], b[1]);
                mma_bf16(acc[0][2*np+1], a0, b[2], b[3]);
                mma_bf16(acc[1][2*np+0], a1, b[0], b[1]);
                mma_bf16(acc[1][2*np+1], a1, b[2], b[3]);
            }
        }

        #pragma unroll
        for (int mt = 0; mt < 2; mt++) {
            #pragma unroll
            for (int rh = 0; rh < 2; rh++) {
                int s = mt*2 + rh;
                float v[16];
                float vm = -INFINITY;
                #pragma unroll
                for (int nt = 0; nt < 8; nt++) {
                    v[2*nt+0] = acc[mt][nt][rh*2+0] * scale;
                    v[2*nt+1] = acc[mt][nt][rh*2+1] * scale;
                    vm = fmaxf(vm, fmaxf(v[2*nt], v[2*nt+1]));
                }
                vm = fmaxf(vm, __shfl_xor_sync(0xffffffffu, vm, 1));
                vm = fmaxf(vm, __shfl_xor_sync(0xffffffffu, vm, 2));
                float mn = fmaxf(mrun[s], vm);
                float es = 0.0f;
                #pragma unroll
                for (int i = 0; i < 16; i++) es += __expf(v[i] - mn);
                es += __shfl_xor_sync(0xffffffffu, es, 1);
                es += __shfl_xor_sync(0xffffffffu, es, 2);
                srun[s] = srun[s] * __expf(mrun[s] - mn) + es;
                mrun[s] = mn;
            }
        }
    }

    if ((lane & 3) == 0) {
        int gid = lane >> 2;
        int slot = blockIdx.y*2 + ng;
        #pragma unroll
        for (int mt = 0; mt < 2; mt++) {
            #pragma unroll
            for (int rh = 0; rh < 2; rh++) {
                int s = mt*2 + rh;
                int row = m0 + mg*32 + mt*16 + rh*8 + gid;
                pm[row*PPART + slot] = mrun[s];
                ps[row*PPART + slot] = srun[s];
            }
        }
    }
}

// ------------------------- gumbel-softmax (soft, in-place) + hard argmax -------------------------
__global__ void k_softmax_gumbel(float* __restrict__ Lm, const float* __restrict__ uS,
                                 const float* __restrict__ uH, float* __restrict__ assignOut) {
    int b = blockIdx.x, t = threadIdx.x;
    __shared__ float sh[8];
    __shared__ float shv[8];
    __shared__ int shi[8];
    float4* L4 = reinterpret_cast<float4*>(Lm) + b*(CK/4);
    float4 l = L4[t];
    float4 us = (reinterpret_cast<const float4*>(uS) + b*(CK/4))[t];
    float4 uh = (reinterpret_cast<const float4*>(uH) + b*(CK/4))[t];
    float zs[4] = { (l.x + gumbelf(us.x))*2.0f, (l.y + gumbelf(us.y))*2.0f,
                    (l.z + gumbelf(us.z))*2.0f, (l.w + gumbelf(us.w))*2.0f };
    float zh[4] = { l.x + gumbelf(uh.x), l.y + gumbelf(uh.y),
                    l.z + gumbelf(uh.z), l.w + gumbelf(uh.w) };
    float vm = fmaxf(fmaxf(zs[0], zs[1]), fmaxf(zs[2], zs[3]));
    #pragma unroll
    for (int o = 16; o; o >>= 1) vm = fmaxf(vm, __shfl_xor_sync(0xffffffffu, vm, o));
    if ((t & 31) == 0) sh[t >> 5] = vm;
    __syncthreads();
    float bm = sh[0];
    #pragma unroll
    for (int i = 1; i < 8; i++) bm = fmaxf(bm, sh[i]);
    float e[4];
    float es = 0.0f;
    #pragma unroll
    for (int j = 0; j < 4; j++) { e[j] = __expf(zs[j] - bm); es += e[j]; }
    #pragma unroll
    for (int o = 16; o; o >>= 1) es += __shfl_xor_sync(0xffffffffu, es, o);
    __syncthreads();
    if ((t & 31) == 0) sh[t >> 5] = es;
    __syncthreads();
    float S = 0.0f;
    #pragma unroll
    for (int i = 0; i < 8; i++) S += sh[i];
    float inv = 1.0f / S;
    L4[t] = make_float4(e[0]*inv, e[1]*inv, e[2]*inv, e[3]*inv);
    float bv = zh[0]; int bi = t*4;
    #pragma unroll
    for (int j = 1; j < 4; j++) if (zh[j] > bv) { bv = zh[j]; bi = t*4 + j; }
    #pragma unroll
    for (int o = 16; o; o >>= 1) {
        float ov = __shfl_xor_sync(0xffffffffu, bv, o);
        int   oi = __shfl_xor_sync(0xffffffffu, bi, o);
        if (ov > bv || (ov == bv && oi < bi)) { bv = ov; bi = oi; }
    }
    if ((t & 31) == 0) { shv[t >> 5] = bv; shi[t >> 5] = bi; }
    __syncthreads();
    if (t == 0 && assignOut) {
        float fbv = shv[0]; int fbi = shi[0];
        #pragma unroll
        for (int i = 1; i < 8; i++)
            if (shv[i] > fbv || (shv[i] == fbv && shi[i] < fbi)) { fbv = shv[i]; fbi = shi[i]; }
        assignOut[b] = (float)fbi;
    }
}

// column sums of assign [CB, CK] -> norm[CK]
__global__ void k_colsum(const float* __restrict__ A, float* __restrict__ norm) {
    int col = blockIdx.x * 256 + threadIdx.x;
    float s0 = 0, s1 = 0, s2 = 0, s3 = 0;
    for (int b = 0; b < CB; b += 4) {
        s0 += A[(b+0)*CK + col];
        s1 += A[(b+1)*CK + col];
        s2 += A[(b+2)*CK + col];
        s3 += A[(b+3)*CK + col];
    }
    norm[col] = (s0 + s1) + (s2 + s3);
}

// per-row dot of two [R,256] matrices (l_pos)
__global__ void k_rowdot(const float* __restrict__ A, const float* __restrict__ Bv,
                         float* __restrict__ out) {
    int r = blockIdx.x, t = threadIdx.x;  // 32 threads
    const float4* a4 = reinterpret_cast<const float4*>(A) + r*64;
    const float4* b4 = reinterpret_cast<const float4*>(Bv) + r*64;
    float4 a = a4[t], b = b4[t];
    float s = a.x*b.x + a.y*b.y + a.z*b.z + a.w*b.w;
    a = a4[t + 32]; b = b4[t + 32];
    s += a.x*b.x + a.y*b.y + a.z*b.z + a.w*b.w;
    #pragma unroll
    for (int o = 16; o; o >>= 1) s += __shfl_xor_sync(0xffffffffu, s, o);
    if (t == 0) out[r] = s;
}

__device__ __forceinline__ float blockReduceSum1024(float v, float* sh) {
    int t = threadIdx.x;
    #pragma unroll
    for (int o = 16; o; o >>= 1) v += __shfl_xor_sync(0xffffffffu, v, o);
    if ((t & 31) == 0) sh[t >> 5] = v;
    __syncthreads();
    float s = 0.0f;
    if (t < 32) {
        s = sh[t];
        #pragma unroll
        for (int o = 16; o; o >>= 1) s += __shfl_xor_sync(0xffffffffu, s, o);
    }
    return s;
}

__global__ void k_final(const float* __restrict__ pmN, const float* __restrict__ psN,
                        const float* __restrict__ lposN,
                        const float* __restrict__ pmK, const float* __restrict__ psK,
                        const float* __restrict__ lposK,
                        float* __restrict__ outLoss) {
    int t = threadIdx.x;
    __shared__ float sh[32];
    float accN = 0.0f;
    for (int r = t; r < CB; r += 1024) {
        float lp = lposN[r] * INV_TEMP;
        float m = lp, s = 1.0f;
        #pragma unroll
        for (int p = 0; p < PPART; p++) {
            float mp = pmN[r*PPART + p], sp = psN[r*PPART + p];
            float mn = fmaxf(m, mp);
            s = s * __expf(m - mn) + sp * __expf(mp - mn);
            m = mn;
        }
        accN += m + logf(s) - lp;
    }
    float sumN = blockReduceSum1024(accN, sh);
    __syncthreads();
    float accK = 0.0f;
    {
        int r = t;
        float lp = lposK[r] * INV_TEMP;
        float m = lp, s = 1.0f;
        #pragma unroll
        for (int p = 0; p < PPART; p++) {
            float mp = pmK[r*PPART + p], sp = psK[r*PPART + p];
            float mn = fmaxf(m, mp);
            s = s * __expf(m - mn) + sp * __expf(mp - mn);
            m = mn;
        }
        accK = m + logf(s) - lp;
    }
    float sumK = blockReduceSum1024(accK, sh);
    if (t == 0) *outLoss = sumN / (float)CB + sumK / (float)CK;
}

// ------------------------- host launcher -------------------------
extern "C" void kernel_launch(void* const* d_in, const int* in_sizes, int n_in,
                              void* d_out, int out_size) {
    const float* x1       = (const float*)d_in[0];
    const float* x2       = (const float*)d_in[1];
    const float* W1       = (const float*)d_in[2];
    const float* W2       = (const float*)d_in[3];
    const float* context1 = (const float*)d_in[4];
    const float* context2 = (const float*)d_in[5];
    const float* queue_n  = (const float*)d_in[6];
    const float* queue_k  = (const float*)d_in[7];
    const float* u1a      = (const float*)d_in[8];
    const float* u1b      = (const float*)d_in[9];
    const float* u2a      = (const float*)d_in[10];
    const float* u2b      = (const float*)d_in[11];
    const float* qnoise   = (const float*)d_in[12];

    float* out       = (float*)d_out;
    float* outAssign = out;
    float* outF2     = out + CB;
    float* outAggk2  = outF2 + (size_t)CB*CD;
    float* outLoss   = outAggk2 + (size_t)CK*CD;

    float *pF1, *pRawF, *pL, *pAggraw, *pAggk1, *pCpart,
          *pNorm1, *pNorm2, *pLposN, *pLposK, *pPmN, *pPsN, *pPmK, *pPsK;
    __nv_bfloat16 *pXh, *pXl, *pWth, *pWtl, *pF1h, *pF1l, *pF2h, *pF2l,
                  *pCtxh, *pCtxl, *pLTh, *pLTl, *pFTh, *pFTl,
                  *pAggk1b, *pQnb, *pQkb;
    cudaGetSymbolAddress((void**)&pF1,     g_F1);
    cudaGetSymbolAddress((void**)&pRawF,   g_rawF);
    cudaGetSymbolAddress((void**)&pL,      g_L);
    cudaGetSymbolAddress((void**)&pAggraw, g_aggraw);
    cudaGetSymbolAddress((void**)&pAggk1,  g_aggk1);
    cudaGetSymbolAddress((void**)&pCpart,  g_Cpart);
    cudaGetSymbolAddress((void**)&pNorm1,  g_norm1);
    cudaGetSymbolAddress((void**)&pNorm2,  g_norm2);
    cudaGetSymbolAddress((void**)&pLposN,  g_lposN);
    cudaGetSymbolAddress((void**)&pLposK,  g_lposK);
    cudaGetSymbolAddress((void**)&pPmN,    g_pmN);
    cudaGetSymbolAddress((void**)&pPsN,    g_psN);
    cudaGetSymbolAddress((void**)&pPmK,    g_pmK);
    cudaGetSymbolAddress((void**)&pPsK,    g_psK);
    cudaGetSymbolAddress((void**)&pXh,     g_xh);
    cudaGetSymbolAddress((void**)&pXl,     g_xl);
    cudaGetSymbolAddress((void**)&pWth,    g_wth);
    cudaGetSymbolAddress((void**)&pWtl,    g_wtl);
    cudaGetSymbolAddress((void**)&pF1h,    g_F1h);
    cudaGetSymbolAddress((void**)&pF1l,    g_F1l);
    cudaGetSymbolAddress((void**)&pF2h,    g_F2h);
    cudaGetSymbolAddress((void**)&pF2l,    g_F2l);
    cudaGetSymbolAddress((void**)&pCtxh,   g_ctxh);
    cudaGetSymbolAddress((void**)&pCtxl,   g_ctxl);
    cudaGetSymbolAddress((void**)&pLTh,    g_LTh);
    cudaGetSymbolAddress((void**)&pLTl,    g_LTl);
    cudaGetSymbolAddress((void**)&pFTh,    g_FTh);
    cudaGetSymbolAddress((void**)&pFTl,    g_FTl);
    cudaGetSymbolAddress((void**)&pAggk1b, g_aggk1b);
    cudaGetSymbolAddress((void**)&pQnb,    g_qnb);
    cudaGetSymbolAddress((void**)&pQkb,    g_qkb);

    cudaFuncSetAttribute(k_lse_mma, cudaFuncAttributeMaxDynamicSharedMemorySize, LSE_SMEM);
    cudaFuncSetAttribute(k_mma3, cudaFuncAttributeMaxDynamicSharedMemorySize, GT_SMEM);

    dim3 t328(32, 8);

    // queues -> bf16 (LSE operands)
    k_l2norm<<<CL, 64>>>(queue_n, nullptr, pQnb, nullptr, nullptr);
    k_queue_combine<<<CKQ, 64>>>(queue_k, qnoise, pQkb);

    // ---- view 1 features: F1 = l2norm(x1 @ W1) ----
    k_tsplit<<<dim3(CD/32, CDIN/32), t328>>>(W1, pWth, pWtl, CDIN, CD);
    k_split<<<CB*CDIN/4/256, 256>>>(x1, pXh, pXl);
    k_mma3<<<dim3(CB/128, CD/128, 2), 256, GT_SMEM>>>(pXh, pXl, pWth, pWtl, pCpart, CB, CD, CDIN, 2);
    k_reduce<<<CB*CD/256, 256>>>(pCpart, pRawF, CB*CD, 2);
    k_l2norm<<<CB, 64>>>(pRawF, pF1, pF1h, pF1l, nullptr);

    // ---- view 2 features: F2 = l2norm(x2 @ W2) (output 1) ----
    k_tsplit<<<dim3(CD/32, CDIN/32), t328>>>(W2, pWth, pWtl, CDIN, CD);
    k_split<<<CB*CDIN/4/256, 256>>>(x2, pXh, pXl);
    k_mma3<<<dim3(CB/128, CD/128, 2), 256, GT_SMEM>>>(pXh, pXl, pWth, pWtl, pCpart, CB, CD, CDIN, 2);
    k_reduce<<<CB*CD/256, 256>>>(pCpart, pRawF, CB*CD, 2);
    k_l2norm<<<CB, 64>>>(pRawF, outF2, pF2h, pF2l, nullptr);

    // ---- view 1: logits -> softmax -> agg ----
    k_l2norm<<<CK, 64>>>(context1, nullptr, pCtxh, pCtxl, nullptr);
    k_mma3<<<dim3(CB/128, CK/128, 1), 256, GT_SMEM>>>(pF1h, pF1l, pCtxh, pCtxl, pL, CB, CK, CD, 1);
    k_softmax_gumbel<<<CB, 256>>>(pL, u1a, u1b, outAssign);
    k_colsum<<<CK/256, 256>>>(pL, pNorm1);
    k_tsplit<<<dim3(CK/32, CB/32), t328>>>(pL, pLTh, pLTl, CB, CK);
    k_tsplit<<<dim3(CD/32, CB/32), t328>>>(pF1, pFTh, pFTl, CB, CD);
    k_mma3<<<dim3(CK/128, CD/128, 8), 256, GT_SMEM>>>(pLTh, pLTl, pFTh, pFTl, pCpart, CK, CD, CB, 8);
    k_reduce<<<CK*CD/256, 256>>>(pCpart, pAggraw, CK*CD, 8);
    k_l2norm<<<CK, 64>>>(pAggraw, pAggk1, pAggk1b, nullptr, pNorm1);

    // ---- view 2: logits -> softmax -> agg (output 2) ----
    k_l2norm<<<CK, 64>>>(context2, nullptr, pCtxh, pCtxl, nullptr);
    k_mma3<<<dim3(CB/128, CK/128, 1), 256, GT_SMEM>>>(pF2h, pF2l, pCtxh, pCtxl, pL, CB, CK, CD, 1);
    k_softmax_gumbel<<<CB, 256>>>(pL, u2a, u2b, nullptr);
    k_colsum<<<CK/256, 256>>>(pL, pNorm2);
    k_tsplit<<<dim3(CK/32, CB/32), t328>>>(pL, pLTh, pLTl, CB, CK);
    k_tsplit<<<dim3(CD/32, CB/32), t328>>>(outF2, pFTh, pFTl, CB, CD);
    k_mma3<<<dim3(CK/128, CD/128, 8), 256, GT_SMEM>>>(pLTh, pLTl, pFTh, pFTl, pCpart, CK, CD, CB, 8);
    k_reduce<<<CK*CD/256, 256>>>(pCpart, pAggraw, CK*CD, 8);
    k_l2norm<<<CK, 64>>>(pAggraw, outAggk2, nullptr, nullptr, pNorm2);

    // positives (fp32)
    k_rowdot<<<CB, 32>>>(pF1, outF2, pLposN);
    k_rowdot<<<CK, 32>>>(pAggk1, outAggk2, pLposK);

    // HMMA streamed GEMM + logsumexp over negatives
    k_lse_mma<<<dim3(CB/128, PSPLIT), 256, LSE_SMEM>>>(pF1h, pQnb, pPmN, pPsN, CL/PSPLIT, INV_TEMP);
    k_lse_mma<<<dim3(CK/128, PSPLIT), 256, LSE_SMEM>>>(pAggk1b, pQkb, pPmK, pPsK, CKQ/PSPLIT, INV_TEMP);

    // final scalar loss
    k_final<<<1, 1024>>>(pPmN, pPsN, pLposN, pPmK, pPsK, pLposK, outLoss);
}